// round 5
// baseline (speedup 1.0000x reference)
#include <cuda_runtime.h>

// C51 categorical projection — GATHER formulation.
// reward [BS], probs [BS,51], not_done [BS] -> new_probs [BS,51]
//
// b(j) = clamp(c + s*j, 0, 50),  s = 0.99*nd in {0, 0.99},
// c = 2.5*(reward + 10 - 10*s).
//
// out[k] = sum_j [floor(b)==k]*(1-frac(b))*p[j] + [ceil(b)==k]*frac(b)*p[j]
// (frac==0 integer case folds in: weight (1-0)=1 at floor, 0 at ceil — matches
//  the reference's (u + (l==u) - b) / (b - l) weights.)
//
// s=0.99: contributing j's lie in ((k-1-c)/s, (k+1-c)/s), width 2.0202 ->
//   <=3 integers; closed-form window, uniform loop count across a warp.
//   Window-boundary contributions vanish continuously, so ulp-level rounding
//   of the window bound is harmless.
// s=0:    all atoms map to one b; probs sum to 1 (normalized input), so the
//   output is closed-form with no probs loads at all.
//
// One thread per OUTPUT element: no smem, no sync, no scatter, full occupancy.

constexpr int A = 51;

__global__ __launch_bounds__(256)
void cat_proj_gather(const float* __restrict__ reward,
                     const float* __restrict__ probs,
                     const float* __restrict__ not_done,
                     float* __restrict__ out,
                     int n_el, int bs)
{
    int e = blockIdx.x * 256 + threadIdx.x;
    if (e >= n_el) return;

    int r = e / A;            // row  (const-div -> mul/shift)
    int k = e - r * A;        // output bin

    float rw = reward[r];
    float nd = not_done[r];

    float outv;
    if (nd == 0.0f) {
        // all mass collapses to b* = clamp(2.5*(rw+10), 0, 50); sum(p)=1
        float b  = fminf(fmaxf(2.5f * (rw + 10.0f), 0.0f), 50.0f);
        float lf = floorf(b);
        float fr = b - lf;
        int   li = (int)lf;
        outv = (k == li) ? (1.0f - fr) : ((k == li + 1) ? fr : 0.0f);
    } else {
        const float S     = 0.99f;
        const float INV_S = 1.0f / 0.99f;
        const float c     = 2.5f * (rw + 10.0f - 10.0f * S);  // same fp path as prior rounds

        int jlo, jhi;
        if (k == 0) {
            jlo = 0;
            jhi = min(A - 1, (int)((1.0f - c) * INV_S) + 1);   // may be <0 -> empty
        } else if (k == A - 1) {
            jlo = max(0, (int)ceilf((49.0f - c) * INV_S) - 1);
            jhi = A - 1;
        } else {
            jlo = (int)ceilf(((float)(k - 1) - c) * INV_S);
            jhi = jlo + 2;
            if (jlo < 0) jlo = 0;
            if (jhi > A - 1) jhi = A - 1;
        }

        const float* prow = probs + r * A;
        float acc = 0.0f;
        for (int j = jlo; j <= jhi; j++) {
            float p  = prow[j];
            float b  = fminf(fmaxf(fmaf(S, (float)j, c), 0.0f), 50.0f);
            float lf = floorf(b);
            float fr = b - lf;
            int   li = (int)lf;
            // weight to bin k: (li==k) -> 1-fr   (covers fr==0 integer case)
            //                  (li==k-1) -> fr   (fr==0 adds 0, harmless)
            float w = (li == k) ? (1.0f - fr) : ((li == k - 1) ? fr : 0.0f);
            acc = fmaf(w, p, acc);
        }
        outv = acc;
    }

    out[e] = outv;
}

extern "C" void kernel_launch(void* const* d_in, const int* in_sizes, int n_in,
                              void* d_out, int out_size)
{
    const float* reward   = (const float*)d_in[0];
    const float* probs    = (const float*)d_in[1];
    const float* not_done = (const float*)d_in[2];
    float* out = (float*)d_out;

    const int bs   = in_sizes[0];
    const int n_el = bs * A;
    const int grid = (n_el + 255) / 256;

    cat_proj_gather<<<grid, 256>>>(reward, probs, not_done, out, n_el, bs);
}

// round 6
// speedup vs baseline: 4.5932x; 4.5932x over previous
#include <cuda_runtime.h>
#include <cstdint>

// C51 categorical projection — scatter scan + 1D bulk-async (TMA) tile I/O.
//
// b(j) = clamp(c + s*j, 0, 50), s = 0.99*nd, c = 2.5*(reward + 10 - 10*s).
// floor(b) nondecreasing, step in {0,1}: two live bins in registers, bin
// emitted with one predicated STS when k advances.
//
// SMEM rows are PACKED (stride 51) so the smem tile is byte-identical to the
// gmem tile: stage-in and copy-out are single cp.async.bulk copies (no
// per-thread LDG/STG/transpose at all). Packed rows are bank-conflict-free
// for row-owner scalar access: word 51*t + j -> bank (19t + j) mod 32,
// gcd(19,32)=1 => bijection over lanes.

constexpr int A           = 51;
constexpr int RPB         = 256;
constexpr int TILE_FLOATS = RPB * A;            // 13056
constexpr int TILE_BYTES  = TILE_FLOATS * 4;    // 52224 (multiple of 16)
constexpr int SMEM_BYTES  = 16 + 2 * TILE_BYTES;  // mbar pad + stage + acc

__device__ __forceinline__ uint32_t smem_u32(const void* p) {
    uint32_t a;
    asm("{ .reg .u64 t; cvta.to.shared.u64 t, %1; cvt.u32.u64 %0, t; }"
        : "=r"(a) : "l"(p));
    return a;
}

__global__ __launch_bounds__(RPB, 2)
void cat_proj_kernel(const float* __restrict__ reward,
                     const float* __restrict__ probs,
                     const float* __restrict__ not_done,
                     float* __restrict__ out,
                     int bs)
{
    extern __shared__ float smraw[];            // 16B-aligned
    uint64_t* mbar  = (uint64_t*)smraw;         // [0,8)
    float*    stage = smraw + 4;                // packed [RPB][51]
    float*    acc   = stage + TILE_FLOATS;      // packed [RPB][51]

    const int tid   = threadIdx.x;
    const int rbase = blockIdx.x * RPB;
    const int rows  = min(RPB, bs - rbase);
    const bool full = (rows == RPB);

    const uint32_t mbar_a  = smem_u32(mbar);
    const uint32_t stage_a = smem_u32(stage);
    const uint32_t acc_a   = smem_u32(acc);

    if (tid == 0)
        asm volatile("mbarrier.init.shared.b64 [%0], 1;" :: "r"(mbar_a) : "memory");
    __syncthreads();

    // ── stage-in: one bulk async copy (full blocks), scalar fallback (tail)
    const float* gsrc = probs + (size_t)rbase * A;
    if (full) {
        if (tid == 0) {
            asm volatile("mbarrier.arrive.expect_tx.shared.b64 _, [%0], %1;"
                         :: "r"(mbar_a), "r"((uint32_t)TILE_BYTES) : "memory");
            asm volatile(
                "cp.async.bulk.shared::cluster.global.mbarrier::complete_tx::bytes "
                "[%0], [%1], %2, [%3];"
                :: "r"(stage_a), "l"(gsrc), "r"((uint32_t)TILE_BYTES), "r"(mbar_a)
                : "memory");
        }
    } else {
        for (int i = tid; i < rows * A; i += RPB) stage[i] = gsrc[i];
    }

    // ── overlap with the TMA load: per-row scalars + zero the acc tile
    const int grow = rbase + tid;
    float rw = 0.0f, nd = 0.0f;
    if (grow < bs) { rw = reward[grow]; nd = not_done[grow]; }

    float4* acc4 = (float4*)acc;
    const float4 z4 = make_float4(0.f, 0.f, 0.f, 0.f);
    #pragma unroll
    for (int it = 0; it < 13; it++) {
        int idx = tid + it * RPB;
        if (idx < TILE_FLOATS / 4) acc4[idx] = z4;
    }

    // ── wait for stage data, then order zero-stores vs emits
    if (full) {
        uint32_t done = 0;
        while (!done) {
            asm volatile(
                "{ .reg .pred p; "
                "  mbarrier.try_wait.parity.shared.b64 p, [%1], %2; "
                "  selp.b32 %0, 1, 0, p; }"
                : "=r"(done) : "r"(mbar_a), "r"(0u) : "memory");
        }
    }
    __syncthreads();

    // ── scan (one thread per row)
    if (tid < rows) {
        const float* prow = stage + tid * A;
        float pv[A];
        #pragma unroll
        for (int j = 0; j < A; j++) pv[j] = prow[j];

        const float s = 0.99f * nd;
        const float c = 2.5f * (rw + 10.0f - 10.0f * s);

        float b  = fminf(fmaxf(c, 0.0f), 50.0f);
        float lf = floorf(b);
        int   k  = (int)lf;
        float wu = (b - lf) * pv[0];
        float aK  = pv[0] - wu;
        float aK1 = wu;

        float* arow = acc + tid * A;
        #pragma unroll
        for (int j = 1; j < A; j++) {
            b  = fminf(fmaxf(fmaf(s, (float)j, c), 0.0f), 50.0f);
            lf = floorf(b);
            int li = (int)lf;                 // in {k, k+1}
            wu = (b - lf) * pv[j];
            float wl = pv[j] - wu;

            bool adv = (li != k);
            if (adv) arow[k] = aK;            // predicated single STS
            aK  = adv ? aK1  : aK;
            aK1 = adv ? 0.0f : aK1;
            k   = li;

            aK  += wl;
            aK1 += wu;
        }
        int k1 = k + 1; if (k1 > A - 1) k1 = A - 1;
        arow[k1] = aK1;                        // if k==50, aK1==0: benign
        arow[k]  = aK;
    }
    __syncthreads();

    // ── copy-out: one bulk async store (full blocks), scalar fallback (tail)
    float* gdst = out + (size_t)rbase * A;
    if (full) {
        if (tid == 0) {
            asm volatile("fence.proxy.async.shared::cta;" ::: "memory");
            asm volatile(
                "cp.async.bulk.global.shared::cta.bulk_group [%0], [%1], %2;"
                :: "l"(gdst), "r"(acc_a), "r"((uint32_t)TILE_BYTES) : "memory");
            asm volatile("cp.async.bulk.commit_group;" ::: "memory");
            asm volatile("cp.async.bulk.wait_group 0;" ::: "memory");
        }
    } else {
        for (int i = tid; i < rows * A; i += RPB) gdst[i] = acc[i];
    }
}

extern "C" void kernel_launch(void* const* d_in, const int* in_sizes, int n_in,
                              void* d_out, int out_size)
{
    const float* reward   = (const float*)d_in[0];
    const float* probs    = (const float*)d_in[1];
    const float* not_done = (const float*)d_in[2];
    float* out = (float*)d_out;

    const int bs   = in_sizes[0];
    const int grid = (bs + RPB - 1) / RPB;

    cudaFuncSetAttribute(cat_proj_kernel,
                         cudaFuncAttributeMaxDynamicSharedMemorySize,
                         SMEM_BYTES);
    cat_proj_kernel<<<grid, RPB, SMEM_BYTES>>>(reward, probs, not_done, out, bs);
}

// round 7
// speedup vs baseline: 4.8659x; 1.0593x over previous
#include <cuda_runtime.h>
#include <cstdint>

// C51 categorical projection — scatter scan + 1D bulk-async (TMA) tile I/O,
// single IN-PLACE smem tile (52.2 KB) so 3 CTAs/SM fit -> 3 overlapping
// load/scan/store pipelines per SM.
//
// b(j) = clamp(c + s*j, 0, 50), s = 0.99*nd, c = 2.5*(reward + 10 - 10*s).
// floor(b) nondecreasing, step in {0,1}: two live bins in registers, bin
// emitted with one predicated STS when k advances.
//
// Tile rows are PACKED (stride 51): smem tile is byte-identical to the gmem
// tile, so stage-in and copy-out are single cp.async.bulk copies. Packed rows
// are conflict-free for row-owner access: word 51*t + j -> bank (19t+j)%32,
// gcd(19,32)=1 => lane bijection.
//
// In-place: each thread prefetches its row to registers (pv), then zeroes and
// scatters into the same row. Per-thread ownership => no cross-thread hazard.

constexpr int A           = 51;
constexpr int RPB         = 256;
constexpr int TILE_FLOATS = RPB * A;            // 13056
constexpr int TILE_BYTES  = TILE_FLOATS * 4;    // 52224 (multiple of 16)
constexpr int SMEM_BYTES  = 16 + TILE_BYTES;    // mbar pad + tile

__device__ __forceinline__ uint32_t smem_u32(const void* p) {
    uint32_t a;
    asm("{ .reg .u64 t; cvta.to.shared.u64 t, %1; cvt.u32.u64 %0, t; }"
        : "=r"(a) : "l"(p));
    return a;
}

__global__ __launch_bounds__(RPB, 3)
void cat_proj_kernel(const float* __restrict__ reward,
                     const float* __restrict__ probs,
                     const float* __restrict__ not_done,
                     float* __restrict__ out,
                     int bs)
{
    extern __shared__ float smraw[];            // 16B-aligned
    uint64_t* mbar = (uint64_t*)smraw;          // [0,8)
    float*    tile = smraw + 4;                 // packed [RPB][51]

    const int tid   = threadIdx.x;
    const int rbase = blockIdx.x * RPB;
    const int rows  = min(RPB, bs - rbase);
    const bool full = (rows == RPB);

    const uint32_t mbar_a = smem_u32(mbar);
    const uint32_t tile_a = smem_u32(tile);

    if (tid == 0)
        asm volatile("mbarrier.init.shared.b64 [%0], 1;" :: "r"(mbar_a) : "memory");
    __syncthreads();

    // ── stage-in: one bulk async copy (full blocks), scalar fallback (tail)
    const float* gsrc = probs + (size_t)rbase * A;
    if (full) {
        if (tid == 0) {
            asm volatile("mbarrier.arrive.expect_tx.shared.b64 _, [%0], %1;"
                         :: "r"(mbar_a), "r"((uint32_t)TILE_BYTES) : "memory");
            asm volatile(
                "cp.async.bulk.shared::cluster.global.mbarrier::complete_tx::bytes "
                "[%0], [%1], %2, [%3];"
                :: "r"(tile_a), "l"(gsrc), "r"((uint32_t)TILE_BYTES), "r"(mbar_a)
                : "memory");
        }
    } else {
        for (int i = tid; i < rows * A; i += RPB) tile[i] = gsrc[i];
        __syncthreads();
    }

    // ── overlap with the TMA load: per-row scalars
    const int grow = rbase + tid;
    float rw = 0.0f, nd = 0.0f;
    if (grow < bs) { rw = reward[grow]; nd = not_done[grow]; }

    // ── wait for the tile
    if (full) {
        uint32_t done = 0;
        while (!done) {
            asm volatile(
                "{ .reg .pred p; "
                "  mbarrier.try_wait.parity.shared.b64 p, [%1], %2; "
                "  selp.b32 %0, 1, 0, p; }"
                : "=r"(done) : "r"(mbar_a), "r"(0u) : "memory");
        }
    }

    // ── scan (one thread per row), in place
    if (tid < rows) {
        float* row = tile + tid * A;

        // prefetch own row to registers
        float pv[A];
        #pragma unroll
        for (int j = 0; j < A; j++) pv[j] = row[j];

        // zero own row in place (reads done)
        #pragma unroll
        for (int j = 0; j < A; j++) row[j] = 0.0f;

        const float s = 0.99f * nd;
        const float c = 2.5f * (rw + 10.0f - 10.0f * s);

        float b  = fminf(fmaxf(c, 0.0f), 50.0f);
        float lf = floorf(b);
        int   k  = (int)lf;
        float wu = (b - lf) * pv[0];
        float aK  = pv[0] - wu;
        float aK1 = wu;

        #pragma unroll
        for (int j = 1; j < A; j++) {
            b  = fminf(fmaxf(fmaf(s, (float)j, c), 0.0f), 50.0f);
            lf = floorf(b);
            int li = (int)lf;                 // in {k, k+1}
            wu = (b - lf) * pv[j];
            float wl = pv[j] - wu;

            bool adv = (li != k);
            if (adv) row[k] = aK;             // predicated single STS
            aK  = adv ? aK1  : aK;
            aK1 = adv ? 0.0f : aK1;
            k   = li;

            aK  += wl;
            aK1 += wu;
        }
        int k1 = k + 1; if (k1 > A - 1) k1 = A - 1;
        row[k1] = aK1;                         // if k==50, aK1==0: benign
        row[k]  = aK;
    }
    __syncthreads();

    // ── copy-out: one bulk async store (full blocks), scalar fallback (tail)
    float* gdst = out + (size_t)rbase * A;
    if (full) {
        if (tid == 0) {
            asm volatile("fence.proxy.async.shared::cta;" ::: "memory");
            asm volatile(
                "cp.async.bulk.global.shared::cta.bulk_group [%0], [%1], %2;"
                :: "l"(gdst), "r"(tile_a), "r"((uint32_t)TILE_BYTES) : "memory");
            asm volatile("cp.async.bulk.commit_group;" ::: "memory");
            asm volatile("cp.async.bulk.wait_group 0;" ::: "memory");
        }
    } else {
        for (int i = tid; i < rows * A; i += RPB) gdst[i] = tile[i];
    }
}

extern "C" void kernel_launch(void* const* d_in, const int* in_sizes, int n_in,
                              void* d_out, int out_size)
{
    const float* reward   = (const float*)d_in[0];
    const float* probs    = (const float*)d_in[1];
    const float* not_done = (const float*)d_in[2];
    float* out = (float*)d_out;

    const int bs   = in_sizes[0];
    const int grid = (bs + RPB - 1) / RPB;

    cudaFuncSetAttribute(cat_proj_kernel,
                         cudaFuncAttributeMaxDynamicSharedMemorySize,
                         SMEM_BYTES);
    cat_proj_kernel<<<grid, RPB, SMEM_BYTES>>>(reward, probs, not_done, out, bs);
}

// round 10
// speedup vs baseline: 4.9504x; 1.0174x over previous
#include <cuda_runtime.h>
#include <cstdint>

// C51 categorical projection — scatter scan + 1D bulk-async (TMA) tile I/O,
// IN-PLACE smem tile, small 128-row tiles so ~7 CTAs/SM run overlapping
// load/scan/store pipelines.
//
// b(j) = clamp(c + s*j, 0, 50), s = 0.99*nd, c = 2.5*(reward + 10 - 10*s).
// floor(b) nondecreasing, step in {0,1}: two live bins in registers, bin
// emitted with one predicated STS when k advances.
//
// Tile rows are PACKED (stride 51): smem tile is byte-identical to the gmem
// tile, so stage-in and copy-out are single cp.async.bulk copies. Packed rows
// are conflict-free for row-owner access: word 51*t + j -> bank (19t+j)%32,
// gcd(19,32)=1 => lane bijection.

constexpr int A           = 51;
constexpr int RPB         = 128;
constexpr int TILE_FLOATS = RPB * A;            // 6528
constexpr int TILE_BYTES  = TILE_FLOATS * 4;    // 26112 (multiple of 16)
constexpr int SMEM_BYTES  = 16 + TILE_BYTES;    // mbar pad + tile

__device__ __forceinline__ uint32_t smem_u32(const void* p) {
    uint32_t a;
    asm("{ .reg .u64 t; cvta.to.shared.u64 t, %1; cvt.u32.u64 %0, t; }"
        : "=r"(a) : "l"(p));
    return a;
}

__global__ __launch_bounds__(RPB, 7)
void cat_proj_kernel(const float* __restrict__ reward,
                     const float* __restrict__ probs,
                     const float* __restrict__ not_done,
                     float* __restrict__ out,
                     int bs)
{
    extern __shared__ float smraw[];            // 16B-aligned
    uint64_t* mbar = (uint64_t*)smraw;          // [0,8)
    float*    tile = smraw + 4;                 // packed [RPB][51]

    const int tid   = threadIdx.x;
    const int rbase = blockIdx.x * RPB;
    const int rows  = min(RPB, bs - rbase);
    const bool full = (rows == RPB);

    const uint32_t mbar_a = smem_u32(mbar);
    const uint32_t tile_a = smem_u32(tile);

    if (tid == 0)
        asm volatile("mbarrier.init.shared.b64 [%0], 1;" :: "r"(mbar_a) : "memory");
    __syncthreads();

    // ── stage-in: one bulk async copy (full blocks), scalar fallback (tail)
    const float* gsrc = probs + (size_t)rbase * A;
    if (full) {
        if (tid == 0) {
            asm volatile("mbarrier.arrive.expect_tx.shared.b64 _, [%0], %1;"
                         :: "r"(mbar_a), "r"((uint32_t)TILE_BYTES) : "memory");
            asm volatile(
                "cp.async.bulk.shared::cluster.global.mbarrier::complete_tx::bytes "
                "[%0], [%1], %2, [%3];"
                :: "r"(tile_a), "l"(gsrc), "r"((uint32_t)TILE_BYTES), "r"(mbar_a)
                : "memory");
        }
    } else {
        for (int i = tid; i < rows * A; i += RPB) tile[i] = gsrc[i];
        __syncthreads();
    }

    // ── overlap with the TMA load: per-row scalars
    const int grow = rbase + tid;
    float rw = 0.0f, nd = 0.0f;
    if (grow < bs) { rw = reward[grow]; nd = not_done[grow]; }

    // ── wait for the tile
    if (full) {
        uint32_t done = 0;
        while (!done) {
            asm volatile(
                "{ .reg .pred p; "
                "  mbarrier.try_wait.parity.shared.b64 p, [%1], %2; "
                "  selp.b32 %0, 1, 0, p; }"
                : "=r"(done) : "r"(mbar_a), "r"(0u) : "memory");
        }
    }

    // ── scan (one thread per row), in place
    if (tid < rows) {
        float* row = tile + tid * A;

        // prefetch own row to registers
        float pv[A];
        #pragma unroll
        for (int j = 0; j < A; j++) pv[j] = row[j];

        // zero own row in place (reads done)
        #pragma unroll
        for (int j = 0; j < A; j++) row[j] = 0.0f;

        const float s = 0.99f * nd;
        const float c = 2.5f * (rw + 10.0f - 10.0f * s);

        float b  = fminf(fmaxf(c, 0.0f), 50.0f);
        float lf = floorf(b);
        int   k  = (int)lf;
        float wu = (b - lf) * pv[0];
        float aK  = pv[0] - wu;
        float aK1 = wu;

        #pragma unroll
        for (int j = 1; j < A; j++) {
            b  = fminf(fmaxf(fmaf(s, (float)j, c), 0.0f), 50.0f);
            lf = floorf(b);
            int li = (int)lf;                 // in {k, k+1}
            wu = (b - lf) * pv[j];
            float wl = pv[j] - wu;

            bool adv = (li != k);
            if (adv) row[k] = aK;             // predicated single STS
            aK  = adv ? aK1  : aK;
            aK1 = adv ? 0.0f : aK1;
            k   = li;

            aK  += wl;
            aK1 += wu;
        }
        int k1 = k + 1; if (k1 > A - 1) k1 = A - 1;
        row[k1] = aK1;                         // if k==50, aK1==0: benign
        row[k]  = aK;
    }
    __syncthreads();

    // ── copy-out: one bulk async store (full blocks), scalar fallback (tail)
    float* gdst = out + (size_t)rbase * A;
    if (full) {
        if (tid == 0) {
            asm volatile("fence.proxy.async.shared::cta;" ::: "memory");
            asm volatile(
                "cp.async.bulk.global.shared::cta.bulk_group [%0], [%1], %2;"
                :: "l"(gdst), "r"(tile_a), "r"((uint32_t)TILE_BYTES) : "memory");
            asm volatile("cp.async.bulk.commit_group;" ::: "memory");
            asm volatile("cp.async.bulk.wait_group 0;" ::: "memory");
        }
    } else {
        for (int i = tid; i < rows * A; i += RPB) gdst[i] = tile[i];
    }
}

extern "C" void kernel_launch(void* const* d_in, const int* in_sizes, int n_in,
                              void* d_out, int out_size)
{
    const float* reward   = (const float*)d_in[0];
    const float* probs    = (const float*)d_in[1];
    const float* not_done = (const float*)d_in[2];
    float* out = (float*)d_out;

    const int bs   = in_sizes[0];
    const int grid = (bs + RPB - 1) / RPB;

    cudaFuncSetAttribute(cat_proj_kernel,
                         cudaFuncAttributeMaxDynamicSharedMemorySize,
                         SMEM_BYTES);
    cat_proj_kernel<<<grid, RPB, SMEM_BYTES>>>(reward, probs, not_done, out, bs);
}